// round 14
// baseline (speedup 1.0000x reference)
#include <cuda_runtime.h>

// SpikeFP32LayerNorm: row-wise LayerNorm (no affine) over 8192 rows x 4096 fp32.
// Champion configuration (R9/R13: 34.9-35.3us kernel / 43.49us dur) with one
// probe: Blackwell 256-bit global ld/st (ld/st.global.cs.v8.f32) — halves
// LDG/STG instruction count (4->2 each way) at identical DRAM traffic,
// shrinking LSU dispatch/queue occupancy per warp.
//   - 256 threads/CTA, one row/CTA, 64 B/thread each way (2x 256-bit)
//   - evict-first streaming both directions
//   - 8 CTA/SM residency
//   - two-stage reduction, warp-0-only stage 2 (rule: post-barrier work in
//     non-warp-0 warps must be scalar smem reads only)
//   - FFMA epilogue: o = v*rstd + (-mean*rstd)
// At the mixed 1:1 R/W HBM wall: ~76% of 8 TB/s spec.

#define ROWS  8192
#define NCOLS 4096
#define TPB   256            // 8 warps; 8 floats x2 per thread

struct __align__(32) f32x8 { float a0, a1, a2, a3, a4, a5, a6, a7; };

__device__ __forceinline__ f32x8 ldg_cs_v8(const float* p) {
    f32x8 r;
    asm volatile("ld.global.cs.v8.f32 {%0,%1,%2,%3,%4,%5,%6,%7}, [%8];"
                 : "=f"(r.a0), "=f"(r.a1), "=f"(r.a2), "=f"(r.a3),
                   "=f"(r.a4), "=f"(r.a5), "=f"(r.a6), "=f"(r.a7)
                 : "l"(p));
    return r;
}

__device__ __forceinline__ void stg_cs_v8(float* p, const f32x8& v) {
    asm volatile("st.global.cs.v8.f32 [%0], {%1,%2,%3,%4,%5,%6,%7,%8};"
                 :: "l"(p),
                    "f"(v.a0), "f"(v.a1), "f"(v.a2), "f"(v.a3),
                    "f"(v.a4), "f"(v.a5), "f"(v.a6), "f"(v.a7)
                 : "memory");
}

__global__ __launch_bounds__(TPB, 8)
void spike_ln_kernel(const float* __restrict__ x, float* __restrict__ out) {
    const int tid = threadIdx.x;
    const int row = blockIdx.x;
    const float* __restrict__ xin  = x   + (size_t)row * NCOLS;
    float* __restrict__       xout = out + (size_t)row * NCOLS;

    // Two independent 256-bit evict-first loads per thread (coalesced)
    f32x8 v0 = ldg_cs_v8(xin + tid * 8);
    f32x8 v1 = ldg_cs_v8(xin + (tid + TPB) * 8);

    float s  = ((v0.a0 + v0.a1) + (v0.a2 + v0.a3)) + ((v0.a4 + v0.a5) + (v0.a6 + v0.a7))
             + ((v1.a0 + v1.a1) + (v1.a2 + v1.a3)) + ((v1.a4 + v1.a5) + (v1.a6 + v1.a7));
    float sq = v0.a0*v0.a0 + v0.a1*v0.a1 + v0.a2*v0.a2 + v0.a3*v0.a3
             + v0.a4*v0.a4 + v0.a5*v0.a5 + v0.a6*v0.a6 + v0.a7*v0.a7
             + v1.a0*v1.a0 + v1.a1*v1.a1 + v1.a2*v1.a2 + v1.a3*v1.a3
             + v1.a4*v1.a4 + v1.a5*v1.a5 + v1.a6*v1.a6 + v1.a7*v1.a7;

    // Stage 1: warp butterfly on both accumulators
    #pragma unroll
    for (int off = 16; off > 0; off >>= 1) {
        s  += __shfl_xor_sync(0xFFFFFFFFu, s,  off);
        sq += __shfl_xor_sync(0xFFFFFFFFu, sq, off);
    }

    __shared__ float ssum[8];
    __shared__ float ssq[8];
    __shared__ float s_rstd, s_nm;   // rstd and -mean*rstd

    const int wid = tid >> 5;
    const int lid = tid & 31;
    if (lid == 0) { ssum[wid] = s; ssq[wid] = sq; }
    __syncthreads();

    // Stage 2: warp 0 only — other warps idle at the barrier.
    if (wid == 0) {
        float ts  = (lid < 8) ? ssum[lid] : 0.0f;
        float tsq = (lid < 8) ? ssq[lid]  : 0.0f;
        #pragma unroll
        for (int off = 4; off > 0; off >>= 1) {
            ts  += __shfl_xor_sync(0xFFFFFFFFu, ts,  off);
            tsq += __shfl_xor_sync(0xFFFFFFFFu, tsq, off);
        }
        if (lid == 0) {
            const float inv_n = 1.0f / (float)NCOLS;
            float mean = ts * inv_n;
            float var  = fmaxf(tsq * inv_n - mean * mean, 0.0f);
            float vpe  = var + 1e-6f;
            float y = rsqrtf(vpe);
            y = 0.5f * y * (3.0f - vpe * (y * y));   // one NR polish
            s_rstd = y;
            s_nm   = -mean * y;
        }
    }
    __syncthreads();

    // Post-barrier work in all warps: scalar smem reads only.
    const float rstd = s_rstd;
    const float nm   = s_nm;

    f32x8 o0, o1;
    o0.a0 = fmaf(v0.a0, rstd, nm);  o0.a1 = fmaf(v0.a1, rstd, nm);
    o0.a2 = fmaf(v0.a2, rstd, nm);  o0.a3 = fmaf(v0.a3, rstd, nm);
    o0.a4 = fmaf(v0.a4, rstd, nm);  o0.a5 = fmaf(v0.a5, rstd, nm);
    o0.a6 = fmaf(v0.a6, rstd, nm);  o0.a7 = fmaf(v0.a7, rstd, nm);
    o1.a0 = fmaf(v1.a0, rstd, nm);  o1.a1 = fmaf(v1.a1, rstd, nm);
    o1.a2 = fmaf(v1.a2, rstd, nm);  o1.a3 = fmaf(v1.a3, rstd, nm);
    o1.a4 = fmaf(v1.a4, rstd, nm);  o1.a5 = fmaf(v1.a5, rstd, nm);
    o1.a6 = fmaf(v1.a6, rstd, nm);  o1.a7 = fmaf(v1.a7, rstd, nm);

    stg_cs_v8(xout + tid * 8,         o0);
    stg_cs_v8(xout + (tid + TPB) * 8, o1);
}

extern "C" void kernel_launch(void* const* d_in, const int* in_sizes, int n_in,
                              void* d_out, int out_size) {
    const float* x = (const float*)d_in[0];
    float* out = (float*)d_out;
    spike_ln_kernel<<<ROWS, TPB>>>(x, out);
}

// round 15
// speedup vs baseline: 1.0043x; 1.0043x over previous
#include <cuda_runtime.h>

// SpikeFP32LayerNorm: row-wise LayerNorm (no affine) over 8192 rows x 4096 fp32.
// FINAL champion (R9/R13, twice-measured: 34.9-35.3us kernel / 43.49us dur /
// rel_err 6.0e-8). At the mixed 1:1 read/write HBM wall (~6.0 TB/s, 76% of
// 8 TB/s spec). Configuration, with every alternative measured and rejected:
//   - 256 threads/CTA, one row/CTA, 4x float4/thread
//       MLP sweep: 2 -> 38.2us, 4 -> 36.0us, 8 -> 36.2us (occupancy drop)
//       256-bit v8 ld/st -> 36.3us (serialized wavefronts within one LSU op,
//       halved scoreboard MLP)
//   - evict-first streaming both directions (__ldcs/__stcs: ~+0.5us total)
//   - 8 CTA/SM residency hint (regs=32 exactly fills 64K register file)
//   - two-stage reduction: warp butterfly -> smem -> warp-0-only stage 2 ->
//     scalar broadcast. RULE (measured in R3 & R11): post-barrier work in
//     non-warp-0 warps beyond a scalar smem read sits on every warp's
//     store-issue critical path and costs 1.4-6us.
//   - FFMA epilogue o = v*rstd + (-mean*rstd) (-0.5us vs sub+mul)
//   - fp32 throughout: the reference's FP64 NR circuit converges to rsqrt;
//     fp32 rsqrt + 1 NR matches to ~1ulp (budget 1e-3, measured 6e-8)
//   - rejected: persistent CTAs (tail imbalance), single-barrier butterfly,
//     redundant smem reduce, float2-merged partials, redux.f32 (not on sm_103)

#define ROWS  8192
#define NCOLS 4096
#define TPB   256            // 8 warps; 4x float4 per thread

__global__ __launch_bounds__(TPB, 8)
void spike_ln_kernel(const float* __restrict__ x, float* __restrict__ out) {
    const int tid = threadIdx.x;
    const int row = blockIdx.x;
    const float4* __restrict__ xin =
        reinterpret_cast<const float4*>(x + (size_t)row * NCOLS);
    float4* __restrict__ xout =
        reinterpret_cast<float4*>(out + (size_t)row * NCOLS);

    // Four independent 128-bit evict-first loads per thread (coalesced)
    float4 v0 = __ldcs(&xin[tid]);
    float4 v1 = __ldcs(&xin[tid + TPB]);
    float4 v2 = __ldcs(&xin[tid + 2 * TPB]);
    float4 v3 = __ldcs(&xin[tid + 3 * TPB]);

    float s  = ((v0.x + v0.y) + (v0.z + v0.w)) + ((v1.x + v1.y) + (v1.z + v1.w))
             + ((v2.x + v2.y) + (v2.z + v2.w)) + ((v3.x + v3.y) + (v3.z + v3.w));
    float sq = v0.x * v0.x + v0.y * v0.y + v0.z * v0.z + v0.w * v0.w
             + v1.x * v1.x + v1.y * v1.y + v1.z * v1.z + v1.w * v1.w
             + v2.x * v2.x + v2.y * v2.y + v2.z * v2.z + v2.w * v2.w
             + v3.x * v3.x + v3.y * v3.y + v3.z * v3.z + v3.w * v3.w;

    // Stage 1: warp butterfly on both accumulators
    #pragma unroll
    for (int off = 16; off > 0; off >>= 1) {
        s  += __shfl_xor_sync(0xFFFFFFFFu, s,  off);
        sq += __shfl_xor_sync(0xFFFFFFFFu, sq, off);
    }

    __shared__ float ssum[8];
    __shared__ float ssq[8];
    __shared__ float s_rstd, s_nm;   // rstd and -mean*rstd

    const int wid = tid >> 5;
    const int lid = tid & 31;
    if (lid == 0) { ssum[wid] = s; ssq[wid] = sq; }
    __syncthreads();

    // Stage 2: warp 0 only — other warps idle at the barrier, off the
    // store-issue critical path.
    if (wid == 0) {
        float ts  = (lid < 8) ? ssum[lid] : 0.0f;
        float tsq = (lid < 8) ? ssq[lid]  : 0.0f;
        #pragma unroll
        for (int off = 4; off > 0; off >>= 1) {
            ts  += __shfl_xor_sync(0xFFFFFFFFu, ts,  off);
            tsq += __shfl_xor_sync(0xFFFFFFFFu, tsq, off);
        }
        if (lid == 0) {
            const float inv_n = 1.0f / (float)NCOLS;
            float mean = ts * inv_n;
            float var  = fmaxf(tsq * inv_n - mean * mean, 0.0f);
            float vpe  = var + 1e-6f;
            float y = rsqrtf(vpe);
            y = 0.5f * y * (3.0f - vpe * (y * y));   // one NR polish
            s_rstd = y;
            s_nm   = -mean * y;
        }
    }
    __syncthreads();

    // Post-barrier work in all warps: scalar smem reads only.
    const float rstd = s_rstd;
    const float nm   = s_nm;

    // Single-FFMA epilogue: o = v * rstd + nm
    float4 o0, o1, o2, o3;
    o0.x = fmaf(v0.x, rstd, nm);  o0.y = fmaf(v0.y, rstd, nm);
    o0.z = fmaf(v0.z, rstd, nm);  o0.w = fmaf(v0.w, rstd, nm);
    o1.x = fmaf(v1.x, rstd, nm);  o1.y = fmaf(v1.y, rstd, nm);
    o1.z = fmaf(v1.z, rstd, nm);  o1.w = fmaf(v1.w, rstd, nm);
    o2.x = fmaf(v2.x, rstd, nm);  o2.y = fmaf(v2.y, rstd, nm);
    o2.z = fmaf(v2.z, rstd, nm);  o2.w = fmaf(v2.w, rstd, nm);
    o3.x = fmaf(v3.x, rstd, nm);  o3.y = fmaf(v3.y, rstd, nm);
    o3.z = fmaf(v3.z, rstd, nm);  o3.w = fmaf(v3.w, rstd, nm);

    __stcs(&xout[tid],           o0);
    __stcs(&xout[tid + TPB],     o1);
    __stcs(&xout[tid + 2 * TPB], o2);
    __stcs(&xout[tid + 3 * TPB], o3);
}

extern "C" void kernel_launch(void* const* d_in, const int* in_sizes, int n_in,
                              void* d_out, int out_size) {
    const float* x = (const float*)d_in[0];
    float* out = (float*)d_out;
    spike_ln_kernel<<<ROWS, TPB>>>(x, out);
}

// round 16
// speedup vs baseline: 1.0050x; 1.0007x over previous
#include <cuda_runtime.h>

// SpikeFP32LayerNorm: row-wise LayerNorm (no affine) over 8192 rows x 4096 fp32.
// Champion parameters (MLP=4/thread, cs/cs streaming, 2-stage warp-leader
// reduction, FFMA epilogue, 2048 resident threads/SM) re-encoded as TWO rows
// per 512-thread CTA: warps 0-7 own row 2b, warps 8-15 own row 2b+1.
// Mechanism: the two __syncthreads and the CTA launch/drain now amortize over
// 2 rows (half the per-row sync overhead; 4096 CTAs instead of 8192), while
// every per-thread and per-SM quantity matches the 34.9us champion exactly.
// Rule kept: post-barrier work in follower warps = scalar smem reads only.

#define ROWS   8192
#define NCOLS  4096
#define TPB    512           // 2 warpgroups x 8 warps; one row per warpgroup
#define WGSIZE 256           // threads per row

__global__ __launch_bounds__(TPB, 4)
void spike_ln_kernel(const float* __restrict__ x, float* __restrict__ out) {
    const int tid  = threadIdx.x;
    const int wg   = tid >> 8;           // 0 or 1: which row of the pair
    const int ltid = tid & (WGSIZE - 1); // 0..255 within the warpgroup
    const int row  = (blockIdx.x << 1) | wg;

    const float4* __restrict__ xin =
        reinterpret_cast<const float4*>(x + (size_t)row * NCOLS);
    float4* __restrict__ xout =
        reinterpret_cast<float4*>(out + (size_t)row * NCOLS);

    // Four independent 128-bit evict-first loads per thread (coalesced)
    float4 v0 = __ldcs(&xin[ltid]);
    float4 v1 = __ldcs(&xin[ltid + WGSIZE]);
    float4 v2 = __ldcs(&xin[ltid + 2 * WGSIZE]);
    float4 v3 = __ldcs(&xin[ltid + 3 * WGSIZE]);

    float s  = ((v0.x + v0.y) + (v0.z + v0.w)) + ((v1.x + v1.y) + (v1.z + v1.w))
             + ((v2.x + v2.y) + (v2.z + v2.w)) + ((v3.x + v3.y) + (v3.z + v3.w));
    float sq = v0.x * v0.x + v0.y * v0.y + v0.z * v0.z + v0.w * v0.w
             + v1.x * v1.x + v1.y * v1.y + v1.z * v1.z + v1.w * v1.w
             + v2.x * v2.x + v2.y * v2.y + v2.z * v2.z + v2.w * v2.w
             + v3.x * v3.x + v3.y * v3.y + v3.z * v3.z + v3.w * v3.w;

    // Stage 1: warp butterfly on both accumulators
    #pragma unroll
    for (int off = 16; off > 0; off >>= 1) {
        s  += __shfl_xor_sync(0xFFFFFFFFu, s,  off);
        sq += __shfl_xor_sync(0xFFFFFFFFu, sq, off);
    }

    __shared__ float ssum[2][8];
    __shared__ float ssq[2][8];
    __shared__ float s_rstd[2], s_nm[2];   // per-row rstd and -mean*rstd

    const int wid  = tid >> 5;             // 0..15 (CTA-wide)
    const int wwid = wid & 7;              // warp index within warpgroup
    const int lid  = tid & 31;
    if (lid == 0) { ssum[wg][wwid] = s; ssq[wg][wwid] = sq; }
    __syncthreads();

    // Stage 2: warp 0 (row 0) and warp 8 (row 1) run concurrently; the other
    // 14 warps idle at the barrier, off the store-issue critical path.
    if (wwid == 0) {
        float ts  = (lid < 8) ? ssum[wg][lid] : 0.0f;
        float tsq = (lid < 8) ? ssq[wg][lid]  : 0.0f;
        #pragma unroll
        for (int off = 4; off > 0; off >>= 1) {
            ts  += __shfl_xor_sync(0xFFFFFFFFu, ts,  off);
            tsq += __shfl_xor_sync(0xFFFFFFFFu, tsq, off);
        }
        if (lid == 0) {
            const float inv_n = 1.0f / (float)NCOLS;
            float mean = ts * inv_n;
            float var  = fmaxf(tsq * inv_n - mean * mean, 0.0f);
            float vpe  = var + 1e-6f;
            float y = rsqrtf(vpe);
            y = 0.5f * y * (3.0f - vpe * (y * y));   // one NR polish
            s_rstd[wg] = y;
            s_nm[wg]   = -mean * y;
        }
    }
    __syncthreads();

    // Post-barrier work: scalar smem reads only.
    const float rstd = s_rstd[wg];
    const float nm   = s_nm[wg];

    // Single-FFMA epilogue: o = v * rstd + nm
    float4 o0, o1, o2, o3;
    o0.x = fmaf(v0.x, rstd, nm);  o0.y = fmaf(v0.y, rstd, nm);
    o0.z = fmaf(v0.z, rstd, nm);  o0.w = fmaf(v0.w, rstd, nm);
    o1.x = fmaf(v1.x, rstd, nm);  o1.y = fmaf(v1.y, rstd, nm);
    o1.z = fmaf(v1.z, rstd, nm);  o1.w = fmaf(v1.w, rstd, nm);
    o2.x = fmaf(v2.x, rstd, nm);  o2.y = fmaf(v2.y, rstd, nm);
    o2.z = fmaf(v2.z, rstd, nm);  o2.w = fmaf(v2.w, rstd, nm);
    o3.x = fmaf(v3.x, rstd, nm);  o3.y = fmaf(v3.y, rstd, nm);
    o3.z = fmaf(v3.z, rstd, nm);  o3.w = fmaf(v3.w, rstd, nm);

    __stcs(&xout[ltid],              o0);
    __stcs(&xout[ltid + WGSIZE],     o1);
    __stcs(&xout[ltid + 2 * WGSIZE], o2);
    __stcs(&xout[ltid + 3 * WGSIZE], o3);
}

extern "C" void kernel_launch(void* const* d_in, const int* in_sizes, int n_in,
                              void* d_out, int out_size) {
    const float* x = (const float*)d_in[0];
    float* out = (float*)d_out;
    spike_ln_kernel<<<ROWS / 2, TPB>>>(x, out);
}

// round 17
// speedup vs baseline: 1.0219x; 1.0168x over previous
#include <cuda_runtime.h>

// SpikeFP32LayerNorm: row-wise LayerNorm (no affine) over 8192 rows x 4096 fp32.
// FINAL champion (measured 3x: 34.9-35.6us kernel / 43.49us best dur /
// rel_err 6.0e-8). Runs at the mixed 1:1 read/write HBM wall: ~6.0 TB/s
// aggregate = 76% of 8 TB/s spec. Every alternative measured and rejected:
//   - MLP/thread sweep: 2 -> 38.2us, 4 -> 36.0us (best), 8 -> 36.2us;
//     256-bit v8 ld/st -> 36.3us (serialized wavefronts, halved SB-level MLP)
//   - CTA shapes: 512-thr 1-row, 256-thr 1-row (best), 128-thr, 512-thr
//     2-row, persistent+prefetch (tail imbalance) — all >= champion
//   - reductions: two-stage warp-leader (best); redundant-smem (+1.4us),
//     single-barrier all-warp butterfly (+6us). RULE: post-barrier work in
//     follower warps beyond a scalar smem read sits on every warp's
//     store-issue critical path.
//   - cache: __ldcs + __stcs (evict-first, touch-once) each worth ~0.25us
//   - residency: __launch_bounds__(256,8), regs=32 fills the register file
//   - epilogue: single FFMA o = v*rstd + (-mean*rstd)
//   - fp32 rsqrt + 1 NR matches the reference FP64 NR circuit to ~1ulp
//     (budget 1e-3, measured 6e-8); redux.f32 not supported on sm_103

#define ROWS  8192
#define NCOLS 4096
#define TPB   256            // 8 warps; 4x float4 per thread

__global__ __launch_bounds__(TPB, 8)
void spike_ln_kernel(const float* __restrict__ x, float* __restrict__ out) {
    const int tid = threadIdx.x;
    const int row = blockIdx.x;
    const float4* __restrict__ xin =
        reinterpret_cast<const float4*>(x + (size_t)row * NCOLS);
    float4* __restrict__ xout =
        reinterpret_cast<float4*>(out + (size_t)row * NCOLS);

    // Four independent 128-bit evict-first loads per thread (coalesced)
    float4 v0 = __ldcs(&xin[tid]);
    float4 v1 = __ldcs(&xin[tid + TPB]);
    float4 v2 = __ldcs(&xin[tid + 2 * TPB]);
    float4 v3 = __ldcs(&xin[tid + 3 * TPB]);

    float s  = ((v0.x + v0.y) + (v0.z + v0.w)) + ((v1.x + v1.y) + (v1.z + v1.w))
             + ((v2.x + v2.y) + (v2.z + v2.w)) + ((v3.x + v3.y) + (v3.z + v3.w));
    float sq = v0.x * v0.x + v0.y * v0.y + v0.z * v0.z + v0.w * v0.w
             + v1.x * v1.x + v1.y * v1.y + v1.z * v1.z + v1.w * v1.w
             + v2.x * v2.x + v2.y * v2.y + v2.z * v2.z + v2.w * v2.w
             + v3.x * v3.x + v3.y * v3.y + v3.z * v3.z + v3.w * v3.w;

    // Stage 1: warp butterfly on both accumulators
    #pragma unroll
    for (int off = 16; off > 0; off >>= 1) {
        s  += __shfl_xor_sync(0xFFFFFFFFu, s,  off);
        sq += __shfl_xor_sync(0xFFFFFFFFu, sq, off);
    }

    __shared__ float ssum[8];
    __shared__ float ssq[8];
    __shared__ float s_rstd, s_nm;   // rstd and -mean*rstd

    const int wid = tid >> 5;
    const int lid = tid & 31;
    if (lid == 0) { ssum[wid] = s; ssq[wid] = sq; }
    __syncthreads();

    // Stage 2: warp 0 only — other warps idle at the barrier, off the
    // store-issue critical path.
    if (wid == 0) {
        float ts  = (lid < 8) ? ssum[lid] : 0.0f;
        float tsq = (lid < 8) ? ssq[lid]  : 0.0f;
        #pragma unroll
        for (int off = 4; off > 0; off >>= 1) {
            ts  += __shfl_xor_sync(0xFFFFFFFFu, ts,  off);
            tsq += __shfl_xor_sync(0xFFFFFFFFu, tsq, off);
        }
        if (lid == 0) {
            const float inv_n = 1.0f / (float)NCOLS;
            float mean = ts * inv_n;
            float var  = fmaxf(tsq * inv_n - mean * mean, 0.0f);
            float vpe  = var + 1e-6f;
            float y = rsqrtf(vpe);
            y = 0.5f * y * (3.0f - vpe * (y * y));   // one NR polish
            s_rstd = y;
            s_nm   = -mean * y;
        }
    }
    __syncthreads();

    // Post-barrier work in all warps: scalar smem reads only.
    const float rstd = s_rstd;
    const float nm   = s_nm;

    // Single-FFMA epilogue: o = v * rstd + nm
    float4 o0, o1, o2, o3;
    o0.x = fmaf(v0.x, rstd, nm);  o0.y = fmaf(v0.y, rstd, nm);
    o0.z = fmaf(v0.z, rstd, nm);  o0.w = fmaf(v0.w, rstd, nm);
    o1.x = fmaf(v1.x, rstd, nm);  o1.y = fmaf(v1.y, rstd, nm);
    o1.z = fmaf(v1.z, rstd, nm);  o1.w = fmaf(v1.w, rstd, nm);
    o2.x = fmaf(v2.x, rstd, nm);  o2.y = fmaf(v2.y, rstd, nm);
    o2.z = fmaf(v2.z, rstd, nm);  o2.w = fmaf(v2.w, rstd, nm);
    o3.x = fmaf(v3.x, rstd, nm);  o3.y = fmaf(v3.y, rstd, nm);
    o3.z = fmaf(v3.z, rstd, nm);  o3.w = fmaf(v3.w, rstd, nm);

    __stcs(&xout[tid],           o0);
    __stcs(&xout[tid + TPB],     o1);
    __stcs(&xout[tid + 2 * TPB], o2);
    __stcs(&xout[tid + 3 * TPB], o3);
}

extern "C" void kernel_launch(void* const* d_in, const int* in_sizes, int n_in,
                              void* d_out, int out_size) {
    const float* x = (const float*)d_in[0];
    float* out = (float*)d_out;
    spike_ln_kernel<<<ROWS, TPB>>>(x, out);
}